// round 3
// baseline (speedup 1.0000x reference)
#include <cuda_runtime.h>

// MeshFit update_points_feat: per-class kNN (K=3) over block-diagonal distance
// matrix + softmax-weighted feature gather.
// C=4, N=4096, M=4096, D=32, K=3. Output (1, C*M, D) float32.
//
// R2 change: 4 queries per WARP (all 32 lanes cooperate on the same 4
// queries; each lane scans n = lane + 32j). One LDS.128 now serves 4
// distance computations -> issue slots/pair 0.37 -> 0.27. Grid = 148 blocks
// (all SMs). 5-step butterfly merge with exact (d, idx) lexicographic order.

#define CC     4
#define NV     4096
#define MV     4096
#define DF     32
#define QPW    4       // queries per warp
#define TB     1024
#define NWARP  (TB / 32)
#define QCHUNK 112     // queries per block (28 active warps)
#define NBX    37      // 37 * 112 = 4144 >= 4096

__device__ __forceinline__ void lex_insert(float t, int ti,
                                           float& d0, float& d1, float& d2,
                                           int& i0, int& i1, int& i2)
{
    if (t < d2 || (t == d2 && ti < i2)) {
        d2 = t; i2 = ti;
        if (d2 < d1 || (d2 == d1 && i2 < i1)) {
            float td = d1; d1 = d2; d2 = td;
            int   tn = i1; i1 = i2; i2 = tn;
        }
        if (d1 < d0 || (d1 == d0 && i1 < i0)) {
            float td = d0; d0 = d1; d1 = td;
            int   tn = i0; i0 = i1; i1 = tn;
        }
    }
}

__global__ void __launch_bounds__(TB, 1)
meshfit_knn_kernel(const float* __restrict__ feat,
                   const float* __restrict__ verts,
                   const float* __restrict__ nverts,
                   float* __restrict__ out)
{
    extern __shared__ float4 pts[];   // NV float4 = 64 KB

    const int c    = blockIdx.y;
    const int tid  = threadIdx.x;
    const int warp = tid >> 5;
    const int lane = tid & 31;

    // Cooperative load of this class's vertices into shared memory.
    const float* vc = verts + (size_t)c * NV * 3;
    for (int i = tid; i < NV; i += TB) {
        pts[i] = make_float4(vc[3 * i + 0], vc[3 * i + 1], vc[3 * i + 2], 0.0f);
    }
    __syncthreads();

    // This warp's 4 queries (same for all lanes).
    const int qbase = blockIdx.x * QCHUNK + warp * QPW;
    if (qbase >= MV) return;               // idle warps (28..31 in most blocks)

    float qx[QPW], qy[QPW], qz[QPW];
#pragma unroll
    for (int j = 0; j < QPW; ++j) {
        int m = qbase + j; if (m > MV - 1) m = MV - 1;   // clamp, store guarded later
        const float* q = nverts + ((size_t)c * MV + m) * 3;
        qx[j] = q[0]; qy[j] = q[1]; qz[j] = q[2];
    }

    // Per-lane top-3 for each query over subsequence n = lane + 32j.
    float d0[QPW], d1[QPW], d2[QPW];
    int   i0[QPW], i1[QPW], i2[QPW];
#pragma unroll
    for (int j = 0; j < QPW; ++j) {
        d0[j] = d1[j] = d2[j] = 3.402823466e38f;
        i0[j] = i1[j] = i2[j] = 0;
    }

#pragma unroll 2
    for (int n = lane; n < NV; n += 32) {
        const float4 p = pts[n];
#pragma unroll
        for (int j = 0; j < QPW; ++j) {
            const float dx = qx[j] - p.x;
            const float dy = qy[j] - p.y;
            const float dz = qz[j] - p.z;
            const float t = dx * dx + dy * dy + dz * dz;
            if (t < d2[j]) {              // rarely taken; per-lane ascending n
                if (t < d1[j]) {
                    d2[j] = d1[j]; i2[j] = i1[j];
                    if (t < d0[j]) { d1[j] = d0[j]; i1[j] = i0[j]; d0[j] = t; i0[j] = n; }
                    else           { d1[j] = t;     i1[j] = n; }
                } else {
                    d2[j] = t; i2[j] = n;
                }
            }
        }
    }

    // Full-warp butterfly merge; lexicographic (d, idx) = exact top_k order.
#pragma unroll
    for (int off = 16; off >= 1; off >>= 1) {
#pragma unroll
        for (int j = 0; j < QPW; ++j) {
            const float pd0 = __shfl_xor_sync(0xffffffffu, d0[j], off);
            const float pd1 = __shfl_xor_sync(0xffffffffu, d1[j], off);
            const float pd2 = __shfl_xor_sync(0xffffffffu, d2[j], off);
            const int   pi0 = __shfl_xor_sync(0xffffffffu, i0[j], off);
            const int   pi1 = __shfl_xor_sync(0xffffffffu, i1[j], off);
            const int   pi2 = __shfl_xor_sync(0xffffffffu, i2[j], off);
            lex_insert(pd0, pi0, d0[j], d1[j], d2[j], i0[j], i1[j], i2[j]);
            lex_insert(pd1, pi1, d0[j], d1[j], d2[j], i0[j], i1[j], i2[j]);
            lex_insert(pd2, pi2, d0[j], d1[j], d2[j], i0[j], i1[j], i2[j]);
        }
    }

    // Global column indices + exact merge of the constant-1.0 off-block fillers.
    const int base  = c * NV;
    const int fbase = (c == 0) ? NV : 0;
    int   g0[QPW], g1[QPW], g2[QPW];
    float w0[QPW], w1[QPW], w2[QPW];
#pragma unroll
    for (int j = 0; j < QPW; ++j) {
        g0[j] = base + i0[j]; g1[j] = base + i1[j]; g2[j] = base + i2[j];
#pragma unroll
        for (int k = 0; k < 3; ++k)
            lex_insert(1.0f, fbase + k, d0[j], d1[j], d2[j], g0[j], g1[j], g2[j]);
        // softmax(-d), max-subtracted (d0 smallest).
        const float e1 = expf(d0[j] - d1[j]);
        const float e2 = expf(d0[j] - d2[j]);
        const float inv = 1.0f / (1.0f + e1 + e2);
        w0[j] = inv; w1[j] = e1 * inv; w2[j] = e2 * inv;
    }

    // Epilogue: lanes 8q..8q+7 write query q's 8 float4 chunks.
    const int qsel  = lane >> 3;     // which of the warp's 4 queries
    const int chunk = lane & 7;      // which float4 of the D=32 row
#define SEL4(a) (qsel < 2 ? (qsel == 0 ? a[0] : a[1]) : (qsel == 2 ? a[2] : a[3]))
    const int   sg0 = SEL4(g0), sg1 = SEL4(g1), sg2 = SEL4(g2);
    const float sw0 = SEL4(w0), sw1 = SEL4(w1), sw2 = SEL4(w2);
#undef SEL4
    const int m_sel = qbase + qsel;
    if (m_sel < MV) {
        const float4 a  = ((const float4*)(feat + (size_t)sg0 * DF))[chunk];
        const float4 b  = ((const float4*)(feat + (size_t)sg1 * DF))[chunk];
        const float4 cv = ((const float4*)(feat + (size_t)sg2 * DF))[chunk];
        float4 r;
        r.x = sw0 * a.x + sw1 * b.x + sw2 * cv.x;
        r.y = sw0 * a.y + sw1 * b.y + sw2 * cv.y;
        r.z = sw0 * a.z + sw1 * b.z + sw2 * cv.z;
        r.w = sw0 * a.w + sw1 * b.w + sw2 * cv.w;
        ((float4*)(out + ((size_t)c * MV + m_sel) * DF))[chunk] = r;
    }
}

extern "C" void kernel_launch(void* const* d_in, const int* in_sizes, int n_in,
                              void* d_out, int out_size)
{
    const float* feat   = (const float*)d_in[0];  // (1, C*N, D)
    const float* verts  = (const float*)d_in[1];  // (C, N, 3)
    const float* nverts = (const float*)d_in[2];  // (C, M, 3)
    float* out = (float*)d_out;                   // (1, C*M, D)

    const int smem = NV * sizeof(float4);         // 64 KB dynamic shared
    cudaFuncSetAttribute(meshfit_knn_kernel,
                         cudaFuncAttributeMaxDynamicSharedMemorySize, smem);

    dim3 grid(NBX, CC);                           // 148 blocks = all SMs
    meshfit_knn_kernel<<<grid, TB, smem>>>(feat, verts, nverts, out);
}

// round 4
// speedup vs baseline: 1.3990x; 1.3990x over previous
#include <cuda_runtime.h>

// MeshFit update_points_feat: per-class exact kNN (K=3) + softmax-weighted
// feature gather. C=4, N=4096, M=4096, D=32. Output (1, C*M, D) float32.
//
// R4: back to R2 layout (8 lanes/query, L=512) + packed f32x2 distance math
// (2 points per instruction chain, negated coords in smem) + 8-point guard
// windows (FMNMX min-tree, single divergent insert region per window).

#define CC     4
#define NV     4096
#define MV     4096
#define DF     32
#define SUBS   8
#define QB     128
#define TB     1024
#define NPAIR  (NV / 2)      // 2048 point-pairs
#define LPP    (NPAIR / SUBS)  // 256 pairs per lane
#define WIN    4               // pairs per guard window (8 points)

typedef unsigned long long u64;

__device__ __forceinline__ u64 pack2(float lo, float hi) {
    u64 r; asm("mov.b64 %0, {%1, %2};" : "=l"(r) : "f"(lo), "f"(hi)); return r;
}
__device__ __forceinline__ void unpack2(u64 v, float& lo, float& hi) {
    asm("mov.b64 {%0, %1}, %2;" : "=f"(lo), "=f"(hi) : "l"(v));
}
__device__ __forceinline__ u64 add2(u64 a, u64 b) {
    u64 r; asm("add.rn.f32x2 %0, %1, %2;" : "=l"(r) : "l"(a), "l"(b)); return r;
}
__device__ __forceinline__ u64 mul2(u64 a, u64 b) {
    u64 r; asm("mul.rn.f32x2 %0, %1, %2;" : "=l"(r) : "l"(a), "l"(b)); return r;
}
__device__ __forceinline__ u64 fma2(u64 a, u64 b, u64 c) {
    u64 r; asm("fma.rn.f32x2 %0, %1, %2, %3;" : "=l"(r) : "l"(a), "l"(b), "l"(c)); return r;
}

__device__ __forceinline__ void lex_insert(float t, int ti,
                                           float& d0, float& d1, float& d2,
                                           int& i0, int& i1, int& i2)
{
    if (t < d2 || (t == d2 && ti < i2)) {
        d2 = t; i2 = ti;
        if (d2 < d1 || (d2 == d1 && i2 < i1)) {
            float td = d1; d1 = d2; d2 = td;
            int   tn = i1; i1 = i2; i2 = tn;
        }
        if (d1 < d0 || (d1 == d0 && i1 < i0)) {
            float td = d0; d0 = d1; d1 = td;
            int   tn = i0; i0 = i1; i1 = tn;
        }
    }
}

// strict-< insert (ascending-index scan => exact top_k tie-break per lane)
__device__ __forceinline__ void ins(float t, int n,
                                    float& d0, float& d1, float& d2,
                                    int& i0, int& i1, int& i2)
{
    if (t < d2) {
        if (t < d1) {
            d2 = d1; i2 = i1;
            if (t < d0) { d1 = d0; i1 = i0; d0 = t; i0 = n; }
            else        { d1 = t;  i1 = n; }
        } else {
            d2 = t; i2 = n;
        }
    }
}

__global__ void __launch_bounds__(TB, 1)
meshfit_knn_kernel(const float* __restrict__ feat,
                   const float* __restrict__ verts,
                   const float* __restrict__ nverts,
                   float* __restrict__ out)
{
    extern __shared__ char smem[];
    float4* sXY = (float4*)smem;                       // 2048 * 16B = 32 KB
    float2* sZ  = (float2*)(smem + NPAIR * 16);        // 2048 * 8B  = 16 KB

    const int c   = blockIdx.y;
    const int tid = threadIdx.x;
    const int sub = tid & (SUBS - 1);
    const int mq  = tid >> 3;
    const int m   = blockIdx.x * QB + mq;

    // Fill smem: pair p = points (2p, 2p+1), NEGATED coords.
    const float* vc = verts + (size_t)c * NV * 3;
    for (int p = tid; p < NPAIR; p += TB) {
        const float* v = vc + 6 * p;
        sXY[p] = make_float4(-v[0], -v[3], -v[1], -v[4]);  // {-x0,-x1,-y0,-y1}
        sZ[p]  = make_float2(-v[2], -v[5]);                // {-z0,-z1}
    }
    __syncthreads();

    const float* q = nverts + ((size_t)c * MV + m) * 3;
    const u64 qxx = pack2(q[0], q[0]);
    const u64 qyy = pack2(q[1], q[1]);
    const u64 qzz = pack2(q[2], q[2]);

    float d0 = 3.402823466e38f, d1 = 3.402823466e38f, d2 = 3.402823466e38f;
    int   i0 = 0, i1 = 0, i2 = 0;

    // Main scan: lane handles pairs p = sub + 8j (points ascending in j).
    for (int jj = 0; jj < LPP; jj += WIN) {
        const int pb = sub + 8 * jj;
        float tl[WIN], th[WIN];
#pragma unroll
        for (int k = 0; k < WIN; ++k) {
            const int p = pb + 8 * k;
            const float4 xy = sXY[p];      // {-x0,-x1,-y0,-y1}
            const float2 zz = sZ[p];       // {-z0,-z1}
            const u64 dX = add2(qxx, pack2(xy.x, xy.y));
            const u64 dY = add2(qyy, pack2(xy.z, xy.w));
            const u64 dZ = add2(qzz, pack2(zz.x, zz.y));
            // t = dz*dz + (dy*dy + dx*dx): same per-element rounding as
            // FMUL + FFMA + FFMA scalar chain.
            const u64 t = fma2(dZ, dZ, fma2(dY, dY, mul2(dX, dX)));
            unpack2(t, tl[k], th[k]);
        }
        // Guard: min of the 8 candidate distances vs current 3rd-best.
        float mab = fminf(fminf(tl[0], th[0]), fminf(tl[1], th[1]));
        float mcd = fminf(fminf(tl[2], th[2]), fminf(tl[3], th[3]));
        if (fminf(mab, mcd) < d2) {
#pragma unroll
            for (int k = 0; k < WIN; ++k) {
                const int p = pb + 8 * k;
                ins(tl[k], 2 * p,     d0, d1, d2, i0, i1, i2);
                ins(th[k], 2 * p + 1, d0, d1, d2, i0, i1, i2);
            }
        }
    }

    // Butterfly merge across the 8 lanes of this query; exact (d, idx) order.
#pragma unroll
    for (int off = 1; off < SUBS; off <<= 1) {
        const float pd0 = __shfl_xor_sync(0xffffffffu, d0, off);
        const float pd1 = __shfl_xor_sync(0xffffffffu, d1, off);
        const float pd2 = __shfl_xor_sync(0xffffffffu, d2, off);
        const int   pi0 = __shfl_xor_sync(0xffffffffu, i0, off);
        const int   pi1 = __shfl_xor_sync(0xffffffffu, i1, off);
        const int   pi2 = __shfl_xor_sync(0xffffffffu, i2, off);
        lex_insert(pd0, pi0, d0, d1, d2, i0, i1, i2);
        lex_insert(pd1, pi1, d0, d1, d2, i0, i1, i2);
        lex_insert(pd2, pi2, d0, d1, d2, i0, i1, i2);
    }

    // Global column indices + exact merge of constant-1.0 off-block fillers.
    const int base = c * NV;
    int g0 = base + i0, g1 = base + i1, g2 = base + i2;
    const int fbase = (c == 0) ? NV : 0;
#pragma unroll
    for (int k = 0; k < 3; ++k)
        lex_insert(1.0f, fbase + k, d0, d1, d2, g0, g1, g2);

    // softmax(-d), max-subtracted (d0 smallest).
    const float e1 = expf(d0 - d1);
    const float e2 = expf(d0 - d2);
    const float inv = 1.0f / (1.0f + e1 + e2);
    const float w0 = inv, w1 = e1 * inv, w2 = e2 * inv;

    // All 8 lanes hold identical top-3; each writes one float4 chunk.
    const float4 a  = ((const float4*)(feat + (size_t)g0 * DF))[sub];
    const float4 b  = ((const float4*)(feat + (size_t)g1 * DF))[sub];
    const float4 cv = ((const float4*)(feat + (size_t)g2 * DF))[sub];
    float4 r;
    r.x = w0 * a.x + w1 * b.x + w2 * cv.x;
    r.y = w0 * a.y + w1 * b.y + w2 * cv.y;
    r.z = w0 * a.z + w1 * b.z + w2 * cv.z;
    r.w = w0 * a.w + w1 * b.w + w2 * cv.w;
    ((float4*)(out + ((size_t)c * MV + m) * DF))[sub] = r;
}

extern "C" void kernel_launch(void* const* d_in, const int* in_sizes, int n_in,
                              void* d_out, int out_size)
{
    const float* feat   = (const float*)d_in[0];  // (1, C*N, D)
    const float* verts  = (const float*)d_in[1];  // (C, N, 3)
    const float* nverts = (const float*)d_in[2];  // (C, M, 3)
    float* out = (float*)d_out;                   // (1, C*M, D)

    const int smem = NPAIR * 16 + NPAIR * 8;      // 48 KB
    cudaFuncSetAttribute(meshfit_knn_kernel,
                         cudaFuncAttributeMaxDynamicSharedMemorySize, smem);

    dim3 grid(MV / QB, CC);                       // 128 blocks
    meshfit_knn_kernel<<<grid, TB, smem>>>(feat, verts, nverts, out);
}

// round 5
// speedup vs baseline: 1.4635x; 1.0461x over previous
#include <cuda_runtime.h>

// MeshFit update_points_feat: per-class exact kNN (K=3) + softmax-weighted
// feature gather. C=4, N=4096, M=4096, D=32. Output (1, C*M, D) float32.
//
// R5: (a) smem pre-packed as ulonglong2/u64 so add.f32x2 consumes LDS results
// directly (no pack MOVs); (b) 16-point guard windows; (c) shared threshold:
// every 4 windows the 8 lanes of a query exchange min(d2) -> guard threshold
// drops ~8x faster, making the skip branch actually skip. Losslessness: every
// lane's running d2 >= global final d2, so skipping windows whose min dist
// exceeds min(tau, d2) can never drop a global-top-3 candidate ('<=' keeps
// boundary ties; strict-'<' ins preserves earliest-index tie-break).

#define CC     4
#define NV     4096
#define MV     4096
#define DF     32
#define SUBS   8
#define QB     128
#define TB     1024
#define NPAIR  (NV / 2)        // 2048 point-pairs
#define LPP    (NPAIR / SUBS)  // 256 pairs per lane
#define WIN    8               // pairs per guard window (16 points)
#define TAUB   4               // windows per threshold refresh

typedef unsigned long long u64;

__device__ __forceinline__ u64 pack2(float lo, float hi) {
    u64 r; asm("mov.b64 %0, {%1, %2};" : "=l"(r) : "f"(lo), "f"(hi)); return r;
}
__device__ __forceinline__ void unpack2(u64 v, float& lo, float& hi) {
    asm("mov.b64 {%0, %1}, %2;" : "=f"(lo), "=f"(hi) : "l"(v));
}
__device__ __forceinline__ u64 add2(u64 a, u64 b) {
    u64 r; asm("add.rn.f32x2 %0, %1, %2;" : "=l"(r) : "l"(a), "l"(b)); return r;
}
__device__ __forceinline__ u64 mul2(u64 a, u64 b) {
    u64 r; asm("mul.rn.f32x2 %0, %1, %2;" : "=l"(r) : "l"(a), "l"(b)); return r;
}
__device__ __forceinline__ u64 fma2(u64 a, u64 b, u64 c) {
    u64 r; asm("fma.rn.f32x2 %0, %1, %2, %3;" : "=l"(r) : "l"(a), "l"(b), "l"(c)); return r;
}

__device__ __forceinline__ void lex_insert(float t, int ti,
                                           float& d0, float& d1, float& d2,
                                           int& i0, int& i1, int& i2)
{
    if (t < d2 || (t == d2 && ti < i2)) {
        d2 = t; i2 = ti;
        if (d2 < d1 || (d2 == d1 && i2 < i1)) {
            float td = d1; d1 = d2; d2 = td;
            int   tn = i1; i1 = i2; i2 = tn;
        }
        if (d1 < d0 || (d1 == d0 && i1 < i0)) {
            float td = d0; d0 = d1; d1 = td;
            int   tn = i0; i0 = i1; i1 = tn;
        }
    }
}

// strict-< insert (ascending-index scan => exact top_k tie-break per lane)
__device__ __forceinline__ void ins(float t, int n,
                                    float& d0, float& d1, float& d2,
                                    int& i0, int& i1, int& i2)
{
    if (t < d2) {
        if (t < d1) {
            d2 = d1; i2 = i1;
            if (t < d0) { d1 = d0; i1 = i0; d0 = t; i0 = n; }
            else        { d1 = t;  i1 = n; }
        } else {
            d2 = t; i2 = n;
        }
    }
}

__global__ void __launch_bounds__(TB, 1)
meshfit_knn_kernel(const float* __restrict__ feat,
                   const float* __restrict__ verts,
                   const float* __restrict__ nverts,
                   float* __restrict__ out)
{
    extern __shared__ char smem[];
    ulonglong2* sXY = (ulonglong2*)smem;               // {xx, yy} per pair: 32 KB
    u64*        sZ  = (u64*)(smem + NPAIR * 16);       // {zz} per pair: 16 KB

    const int c   = blockIdx.y;
    const int tid = threadIdx.x;
    const int sub = tid & (SUBS - 1);
    const int mq  = tid >> 3;
    const int m   = blockIdx.x * QB + mq;

    // Fill smem: pair p = points (2p, 2p+1), NEGATED coords, pre-packed.
    const float* vc = verts + (size_t)c * NV * 3;
    for (int p = tid; p < NPAIR; p += TB) {
        const float* v = vc + 6 * p;
        ulonglong2 e;
        e.x = pack2(-v[0], -v[3]);          // {-x0, -x1}
        e.y = pack2(-v[1], -v[4]);          // {-y0, -y1}
        sXY[p] = e;
        sZ[p]  = pack2(-v[2], -v[5]);       // {-z0, -z1}
    }
    __syncthreads();

    const float* q = nverts + ((size_t)c * MV + m) * 3;
    const u64 qxx = pack2(q[0], q[0]);
    const u64 qyy = pack2(q[1], q[1]);
    const u64 qzz = pack2(q[2], q[2]);

    float d0 = 3.402823466e38f, d1 = 3.402823466e38f, d2 = 3.402823466e38f;
    int   i0 = 0, i1 = 0, i2 = 0;
    float tau = 3.402823466e38f;

    // Main scan: lane handles pairs p = sub + 8j; 32 windows of WIN=8 pairs.
#pragma unroll 1
    for (int jj = 0; jj < LPP; jj += WIN) {
        // Refresh shared threshold every TAUB windows.
        if ((jj & (WIN * TAUB - 1)) == 0) {
            float t2 = d2;
#pragma unroll
            for (int off = 1; off < SUBS; off <<= 1)
                t2 = fminf(t2, __shfl_xor_sync(0xffffffffu, t2, off));
            tau = t2;
        }
        const int pb = sub + 8 * jj;
        float tl[WIN], th[WIN];
#pragma unroll
        for (int k = 0; k < WIN; ++k) {
            const ulonglong2 xy = sXY[pb + 8 * k];   // LDS.128 -> {xx, yy}
            const u64        zz = sZ[pb + 8 * k];    // LDS.64  -> {zz}
            const u64 dX = add2(qxx, xy.x);
            const u64 dY = add2(qyy, xy.y);
            const u64 dZ = add2(qzz, zz);
            const u64 t = fma2(dZ, dZ, fma2(dY, dY, mul2(dX, dX)));
            unpack2(t, tl[k], th[k]);
        }
        // Guard: min of 16 candidate distances vs min(shared tau, local d2).
        float m0 = fminf(fminf(tl[0], th[0]), fminf(tl[1], th[1]));
        float m1 = fminf(fminf(tl[2], th[2]), fminf(tl[3], th[3]));
        float m2 = fminf(fminf(tl[4], th[4]), fminf(tl[5], th[5]));
        float m3 = fminf(fminf(tl[6], th[6]), fminf(tl[7], th[7]));
        const float wmin = fminf(fminf(m0, m1), fminf(m2, m3));
        if (wmin <= fminf(tau, d2)) {
#pragma unroll
            for (int k = 0; k < WIN; ++k) {
                const int p = pb + 8 * k;
                ins(tl[k], 2 * p,     d0, d1, d2, i0, i1, i2);
                ins(th[k], 2 * p + 1, d0, d1, d2, i0, i1, i2);
            }
        }
    }

    // Butterfly merge across the 8 lanes of this query; exact (d, idx) order.
#pragma unroll
    for (int off = 1; off < SUBS; off <<= 1) {
        const float pd0 = __shfl_xor_sync(0xffffffffu, d0, off);
        const float pd1 = __shfl_xor_sync(0xffffffffu, d1, off);
        const float pd2 = __shfl_xor_sync(0xffffffffu, d2, off);
        const int   pi0 = __shfl_xor_sync(0xffffffffu, i0, off);
        const int   pi1 = __shfl_xor_sync(0xffffffffu, i1, off);
        const int   pi2 = __shfl_xor_sync(0xffffffffu, i2, off);
        lex_insert(pd0, pi0, d0, d1, d2, i0, i1, i2);
        lex_insert(pd1, pi1, d0, d1, d2, i0, i1, i2);
        lex_insert(pd2, pi2, d0, d1, d2, i0, i1, i2);
    }

    // Global column indices + exact merge of constant-1.0 off-block fillers.
    const int base = c * NV;
    int g0 = base + i0, g1 = base + i1, g2 = base + i2;
    const int fbase = (c == 0) ? NV : 0;
#pragma unroll
    for (int k = 0; k < 3; ++k)
        lex_insert(1.0f, fbase + k, d0, d1, d2, g0, g1, g2);

    // softmax(-d), max-subtracted (d0 smallest).
    const float e1 = expf(d0 - d1);
    const float e2 = expf(d0 - d2);
    const float inv = 1.0f / (1.0f + e1 + e2);
    const float w0 = inv, w1 = e1 * inv, w2 = e2 * inv;

    // All 8 lanes hold identical top-3; each writes one float4 chunk.
    const float4 a  = ((const float4*)(feat + (size_t)g0 * DF))[sub];
    const float4 b  = ((const float4*)(feat + (size_t)g1 * DF))[sub];
    const float4 cv = ((const float4*)(feat + (size_t)g2 * DF))[sub];
    float4 r;
    r.x = w0 * a.x + w1 * b.x + w2 * cv.x;
    r.y = w0 * a.y + w1 * b.y + w2 * cv.y;
    r.z = w0 * a.z + w1 * b.z + w2 * cv.z;
    r.w = w0 * a.w + w1 * b.w + w2 * cv.w;
    ((float4*)(out + ((size_t)c * MV + m) * DF))[sub] = r;
}

extern "C" void kernel_launch(void* const* d_in, const int* in_sizes, int n_in,
                              void* d_out, int out_size)
{
    const float* feat   = (const float*)d_in[0];  // (1, C*N, D)
    const float* verts  = (const float*)d_in[1];  // (C, N, 3)
    const float* nverts = (const float*)d_in[2];  // (C, M, 3)
    float* out = (float*)d_out;                   // (1, C*M, D)

    const int smem = NPAIR * 16 + NPAIR * 8;      // 48 KB
    cudaFuncSetAttribute(meshfit_knn_kernel,
                         cudaFuncAttributeMaxDynamicSharedMemorySize, smem);

    dim3 grid(MV / QB, CC);                       // 128 blocks
    meshfit_knn_kernel<<<grid, TB, smem>>>(feat, verts, nverts, out);
}